// round 11
// baseline (speedup 1.0000x reference)
#include <cuda_runtime.h>
#include <cuda_fp16.h>
#include <cstdint>

#define BATCH 4
#define DIMC 96
#define HEADS 3
#define NBH 12
#define WSQ 49
#define QK_SCALE 0.17677669529663687f

// ---- k2 geometry ----
#define PXB2 80                      // bytes per px per 32-ch pass (64 + 16 pad)
#define HALO_PX 532                  // 14*38
#define BTAPU2 896                   // uint2 per tap: 4 ks * 7 nt * 32 lanes
#define ATTN_SH_B (256 * 50 * 4)     // 51200
#define INV_SH_B  1024
#define V_SH_B    (14 * 40 * 8 * 4)  // 17920
#define SMEM_K2 (ATTN_SH_B + INV_SH_B + V_SH_B)   // 70144 (halo 42560 fits inside)
#define HALO_N 532

// ---- k1/k3 geometry ----
#define XPAD 132
#define SMEM_G (96 * XPAD * 4)
#define NQKVF (36 * 12 * 32)
#define NPROJF (12 * 12 * 32)

// ---------------- scratch (device globals) ----------------
__device__ __half g_qkh[(size_t)NBH * 128 * 128 * 64];
__device__ float  g_v  [(size_t)NBH * 32 * 128 * 128];
__device__ float  g_att[(size_t)BATCH * DIMC * 128 * 128];
__device__ uint2  g_w2f[(size_t)WSQ * BTAPU2];
__device__ uint2  g_wqkv[NQKVF];
__device__ uint2  g_wproj[NPROJF];

__device__ __forceinline__ uint32_t tf32b(float x) {
    unsigned u;
    asm("cvt.rna.tf32.f32 %0, %1;" : "=r"(u) : "f"(x));
    return u;
}
__device__ __forceinline__ float to_tf32(float x) { return __uint_as_float(tf32b(x)); }

__device__ __forceinline__ void mma_tf32_16n8k8(float* acc, const uint32_t* a, uint2 b) {
    asm volatile(
        "mma.sync.aligned.m16n8k8.row.col.f32.tf32.tf32.f32 "
        "{%0,%1,%2,%3},{%4,%5,%6,%7},{%8,%9},{%0,%1,%2,%3};"
        : "+f"(acc[0]), "+f"(acc[1]), "+f"(acc[2]), "+f"(acc[3])
        : "r"(a[0]), "r"(a[1]), "r"(a[2]), "r"(a[3]), "r"(b.x), "r"(b.y));
}
__device__ __forceinline__ void mma_f16_16n8k16(float* acc, const uint32_t* a, uint2 b) {
    asm volatile(
        "mma.sync.aligned.m16n8k16.row.col.f32.f16.f16.f32 "
        "{%0,%1,%2,%3},{%4,%5,%6,%7},{%8,%9},{%0,%1,%2,%3};"
        : "+f"(acc[0]), "+f"(acc[1]), "+f"(acc[2]), "+f"(acc[3])
        : "r"(a[0]), "r"(a[1]), "r"(a[2]), "r"(a[3]), "r"(b.x), "r"(b.y));
}

// ---------------- K0: pack all weight fragments -----------------------------
__global__ void k0_prep(const float* __restrict__ attn_w,
                        const float* __restrict__ qkv_w,
                        const float* __restrict__ proj_w) {
    int idx = blockIdx.x * 256 + threadIdx.x;
    if (idx < WSQ * BTAPU2) {
        int lane = idx & 31;
        int nt   = (idx >> 5) % 7;
        int ks   = ((idx >> 5) / 7) & 3;
        int s    = idx / (32 * 28);
        int n = nt * 8 + (lane >> 2);
        int k0 = ks * 16 + (lane & 3) * 2;
        __half h[4];
        #pragma unroll
        for (int ii = 0; ii < 2; ++ii)
            h[ii] = (n < WSQ) ? __float2half(attn_w[(n * 64 + k0 + ii) * WSQ + s]) : __half(0.f);
        #pragma unroll
        for (int ii = 0; ii < 2; ++ii)
            h[2 + ii] = (n < WSQ) ? __float2half(attn_w[(n * 64 + k0 + 8 + ii) * WSQ + s]) : __half(0.f);
        uint2 u;
        u.x = *(const uint32_t*)&h[0];
        u.y = *(const uint32_t*)&h[2];
        g_w2f[idx] = u;
        return;
    }
    int i = idx - WSQ * BTAPU2;
    if (i < NQKVF) {
        int lane = i & 31, r = i >> 5;
        int ks = r % 12, nt = r / 12;
        int oc = nt * 8 + (lane >> 2);
        int k  = ks * 8 + (lane & 3);
        uint2 u;
        u.x = tf32b(qkv_w[oc * 96 + k]);
        u.y = tf32b(qkv_w[oc * 96 + k + 4]);
        g_wqkv[i] = u;
        return;
    }
    i -= NQKVF;
    if (i < NPROJF) {
        int lane = i & 31, r = i >> 5;
        int ks = r % 12, nt = r / 12;
        int oc = nt * 8 + (lane >> 2);
        int k  = ks * 8 + (lane & 3);
        uint2 u;
        u.x = tf32b(proj_w[oc * 96 + k]);
        u.y = tf32b(proj_w[oc * 96 + k + 4]);
        g_wproj[i] = u;
    }
}

// ---------------- K1: 1x1 qkv conv via tf32 mma -----------------------------
__global__ __launch_bounds__(256, 2) void k1_qkv(const float* __restrict__ x,
                                                 const float* __restrict__ bias) {
    extern __shared__ float smem[];
    float* xs = smem;
    const int tid = threadIdx.x, lane = tid & 31, wid = tid >> 5;
    const int row = blockIdx.x, b = blockIdx.y;

    const float4* xb = (const float4*)(x + (((size_t)b * DIMC) << 14) + (row << 7));
    #pragma unroll
    for (int it = 0; it < 12; ++it) {
        int idx = tid + it * 256;
        int c = idx >> 5, p4 = idx & 31;
        float4 v = xb[(size_t)c * 4096 + p4];
        v.x = to_tf32(v.x); v.y = to_tf32(v.y); v.z = to_tf32(v.z); v.w = to_tf32(v.w);
        *(float4*)&xs[c * XPAD + p4 * 4] = v;
    }
    __syncthreads();

    const int pr = wid * 16 + (lane >> 2);
    uint32_t A[12][4];
    #pragma unroll
    for (int ks = 0; ks < 12; ++ks) {
        int k0 = ks * 8 + (lane & 3);
        A[ks][0] = __float_as_uint(xs[k0 * XPAD + pr]);
        A[ks][1] = __float_as_uint(xs[k0 * XPAD + pr + 8]);
        A[ks][2] = __float_as_uint(xs[(k0 + 4) * XPAD + pr]);
        A[ks][3] = __float_as_uint(xs[(k0 + 4) * XPAD + pr + 8]);
    }

    const int bh_base = b * HEADS;
    for (int nt = 0; nt < 36; ++nt) {
        uint2 bf[12];
        #pragma unroll
        for (int ks = 0; ks < 12; ++ks) bf[ks] = g_wqkv[(nt * 12 + ks) * 32 + lane];
        float acc[4] = {0.f, 0.f, 0.f, 0.f};
        #pragma unroll
        for (int ks = 0; ks < 12; ++ks) mma_tf32_16n8k8(acc, A[ks], bf[ks]);

        int oc = nt * 8 + ((lane & 3) << 1);
        float b0 = bias[oc], b1 = bias[oc + 1];
        if (nt < 24) {
            int oc96 = oc - (nt < 12 ? 0 : 96);
            int head = oc96 >> 5, ch = (oc96 & 31) + (nt < 12 ? 0 : 32);
            size_t base = ((((size_t)(bh_base + head) * 128 + row) << 7));
            float s = (nt < 12) ? QK_SCALE : 1.0f;
            #pragma unroll
            for (int i = 0; i < 2; ++i) {
                int px = pr + i * 8;
                __half2 h = __floats2half2_rn((acc[2 * i] + b0) * s, (acc[2 * i + 1] + b1) * s);
                *(__half2*)&g_qkh[(base + px) * 64 + ch] = h;
            }
        } else {
            int oc96 = oc - 192;
            int head = oc96 >> 5, ch = oc96 & 31;
            float* vb = g_v + ((((size_t)(bh_base + head) * 32) + ch) << 14) + (row << 7);
            #pragma unroll
            for (int i = 0; i < 2; ++i) {
                int px = pr + i * 8;
                vb[px]             = acc[2 * i] + b0;
                vb[(1 << 14) + px] = acc[2 * i + 1] + b1;
            }
        }
    }
}

// ---------------- K2 v3: 16 warps, 1 mtile/warp, 2-pass K, occupancy-first --
// block: 512 thr, tile 8x32 px. Warp w -> mtile w (16 px) x 7 ntiles (acc 28 regs).
// K split into 2 passes of 32 ch; halo 80 B/px (conflict-free ldmatrix).
// B frags via __ldg (L2-resident stream); 8 warps/SMSP hide the latency.
__global__ __launch_bounds__(512, 2) void k2_attn(const float* __restrict__ attn_b) {
    extern __shared__ char smemk2[];
    float* attn_sh = (float*)smemk2;                       // [256][50]
    float* inv_sh  = (float*)(smemk2 + ATTN_SH_B);         // [256]
    float* v_sh    = (float*)(smemk2 + ATTN_SH_B + INV_SH_B); // [14][40][8]

    const int tid = threadIdx.x;
    const int lane = tid & 31, wid = tid >> 5;
    const int bh  = blockIdx.z;
    const int ty0 = blockIdx.y * 8;
    const int tx0 = blockIdx.x * 32;

    uint32_t sb;
    { uint64_t t_; asm("cvta.to.shared.u64 %0, %1;" : "=l"(t_) : "l"(smemk2)); sb = (uint32_t)t_; }

    // ldmatrix base: mtile = wid -> 16 consecutive px in one image row
    uint32_t abase;
    {
        int p = wid * 16 + (lane & 15);
        abase = sb + (uint32_t)((p >> 5) * 38 + (p & 31)) * PXB2 + (lane >> 4) * 16;
    }

    float acc[7][4];
    #pragma unroll
    for (int nt = 0; nt < 7; ++nt)
        #pragma unroll
        for (int e = 0; e < 4; ++e) acc[nt][e] = 0.0f;

    const uint2* wbase = g_w2f + lane;
    const uint4* qk4 = (const uint4*)g_qkh;

    for (int pass = 0; pass < 2; ++pass) {
        __syncthreads();    // pass1: all warps done with pass0 halo
        // load 32-ch halo: 4 uint4 per px (bytes 64*pass .. +63)
        for (int idx = tid; idx < HALO_PX * 4; idx += 512) {
            int pxi = idx >> 2, g = idx & 3;
            int hy = pxi / 38, hx = pxi - hy * 38;
            int gy = ty0 - 3 + hy, gx = tx0 - 3 + hx;
            uint4 val = make_uint4(0, 0, 0, 0);
            if ((unsigned)gy < 128u && (unsigned)gx < 128u)
                val = qk4[(((((size_t)bh * 128 + gy) << 7) + gx) << 3) + pass * 4 + g];
            *(uint4*)(smemk2 + pxi * PXB2 + g * 16) = val;
        }
        __syncthreads();

        #pragma unroll 1
        for (int s = 0; s < WSQ; ++s) {
            int dy = s / 7, dx = s - dy * 7;
            uint32_t toff = (uint32_t)(dy * 38 + dx) * PXB2;
            const uint2* wtap = wbase + (size_t)s * BTAPU2;
            #pragma unroll
            for (int ks = 0; ks < 2; ++ks) {
                int ksg = pass * 2 + ks;
                uint2 bf[7];
                #pragma unroll
                for (int nt = 0; nt < 7; ++nt) bf[nt] = __ldg(wtap + (ksg * 7 + nt) * 32);
                uint32_t a[4];
                asm volatile("ldmatrix.sync.aligned.m8n8.x4.shared.b16 {%0,%1,%2,%3}, [%4];"
                    : "=r"(a[0]), "=r"(a[1]), "=r"(a[2]), "=r"(a[3])
                    : "r"(abase + toff + ks * 32));
                #pragma unroll
                for (int nt = 0; nt < 7; ++nt) mma_f16_16n8k16(acc[nt], a, bf[nt]);
            }
        }
    }

    __syncthreads();   // halo reads done -> smem becomes attn buffer

    // ---- logits (+bias) to smem ----
    {
        int p0 = wid * 16 + (lane >> 2);
        #pragma unroll
        for (int nt = 0; nt < 7; ++nt) {
            int t0 = nt * 8 + (lane & 3) * 2;
            if (t0 < WSQ) {
                float bb = attn_b[t0];
                attn_sh[p0 * 50 + t0]       = acc[nt][0] + bb;
                attn_sh[(p0 + 8) * 50 + t0] = acc[nt][2] + bb;
            }
            if (t0 + 1 < WSQ) {
                float bb = attn_b[t0 + 1];
                attn_sh[p0 * 50 + t0 + 1]       = acc[nt][1] + bb;
                attn_sh[(p0 + 8) * 50 + t0 + 1] = acc[nt][3] + bb;
            }
        }
    }
    __syncthreads();

    // ---- softmax: thread tid<256 owns pixel tid; exp stored back to smem ----
    if (tid < 256) {
        float mx = -1e30f;
        #pragma unroll
        for (int t = 0; t < WSQ; ++t) mx = fmaxf(mx, attn_sh[tid * 50 + t]);
        float sum = 0.0f;
        #pragma unroll
        for (int t = 0; t < WSQ; ++t) {
            float e = __expf(attn_sh[tid * 50 + t] - mx);
            attn_sh[tid * 50 + t] = e;
            sum += e;
        }
        inv_sh[tid] = 1.0f / sum;
    }

    const int b    = bh / HEADS;
    const int head = bh - b * HEADS;
    const int pxi  = tid & 255;          // pixel this thread handles in AV
    const int sub  = tid >> 8;           // channel half of 8-ch chunk
    const int py = pxi >> 5, pxx = pxi & 31;

    // ---- attn . V (4 chunks of 8 ch; thread-pair splits 8ch into 4+4) ----
    for (int vcblk = 0; vcblk < 4; ++vcblk) {
        __syncthreads();   // first iter: also publishes softmax results
        for (int idx = tid; idx < 8 * HALO_N; idx += 512) {
            int cc = idx / HALO_N;
            int rr = idx - cc * HALO_N;
            int hy = rr / 38, hx = rr - hy * 38;
            int gyy = ty0 - 3 + hy, gxx = tx0 - 3 + hx;
            float val = 0.0f;
            if ((unsigned)gyy < 128u && (unsigned)gxx < 128u)
                val = g_v[((((size_t)bh * 32) + vcblk * 8 + cc) << 14) + (gyy << 7) + gxx];
            v_sh[(hy * 40 + hx) * 8 + cc] = val;
        }
        __syncthreads();

        float o[4] = {0.f, 0.f, 0.f, 0.f};
        const float* arow = attn_sh + pxi * 50;
        #pragma unroll
        for (int dy = 0; dy < 7; ++dy) {
            #pragma unroll
            for (int dx = 0; dx < 7; ++dx) {
                float a = arow[dy * 7 + dx];
                float4 vv = *(const float4*)&v_sh[((py + dy) * 40 + pxx + dx) * 8 + sub * 4];
                o[0] = fmaf(a, vv.x, o[0]); o[1] = fmaf(a, vv.y, o[1]);
                o[2] = fmaf(a, vv.z, o[2]); o[3] = fmaf(a, vv.w, o[3]);
            }
        }
        float inv = inv_sh[pxi];
        #pragma unroll
        for (int vc = 0; vc < 4; ++vc)
            g_att[((((size_t)b * DIMC) + head * 32 + vcblk * 8 + sub * 4 + vc) << 14)
                  + ((ty0 + py) << 7) + (tx0 + pxx)] = o[vc] * inv;
    }
}

// ---------------- K3: 1x1 proj via tf32 mma -> d_out ------------------------
__global__ __launch_bounds__(256, 2) void k3_proj(const float* __restrict__ bias,
                                                  float* __restrict__ out) {
    extern __shared__ float smem[];
    float* xs = smem;
    const int tid = threadIdx.x, lane = tid & 31, wid = tid >> 5;
    const int row = blockIdx.x, b = blockIdx.y;

    const float4* xb = (const float4*)(g_att + (((size_t)b * DIMC) << 14) + (row << 7));
    #pragma unroll
    for (int it = 0; it < 12; ++it) {
        int idx = tid + it * 256;
        int c = idx >> 5, p4 = idx & 31;
        float4 v = xb[(size_t)c * 4096 + p4];
        v.x = to_tf32(v.x); v.y = to_tf32(v.y); v.z = to_tf32(v.z); v.w = to_tf32(v.w);
        *(float4*)&xs[c * XPAD + p4 * 4] = v;
    }
    __syncthreads();

    const int pr = wid * 16 + (lane >> 2);
    uint32_t A[12][4];
    #pragma unroll
    for (int ks = 0; ks < 12; ++ks) {
        int k0 = ks * 8 + (lane & 3);
        A[ks][0] = __float_as_uint(xs[k0 * XPAD + pr]);
        A[ks][1] = __float_as_uint(xs[k0 * XPAD + pr + 8]);
        A[ks][2] = __float_as_uint(xs[(k0 + 4) * XPAD + pr]);
        A[ks][3] = __float_as_uint(xs[(k0 + 4) * XPAD + pr + 8]);
    }

    for (int nt = 0; nt < 12; ++nt) {
        uint2 bf[12];
        #pragma unroll
        for (int ks = 0; ks < 12; ++ks) bf[ks] = g_wproj[(nt * 12 + ks) * 32 + lane];
        float acc[4] = {0.f, 0.f, 0.f, 0.f};
        #pragma unroll
        for (int ks = 0; ks < 12; ++ks) mma_tf32_16n8k8(acc, A[ks], bf[ks]);

        int oc = nt * 8 + ((lane & 3) << 1);
        float b0 = bias[oc], b1 = bias[oc + 1];
        float* ob = out + ((((size_t)b * DIMC) + oc) << 14) + (row << 7);
        #pragma unroll
        for (int i = 0; i < 2; ++i) {
            int px = pr + i * 8;
            ob[px]             = acc[2 * i] + b0;
            ob[(1 << 14) + px] = acc[2 * i + 1] + b1;
        }
    }
}

// ---------------- launch ---------------------------------------------------
extern "C" void kernel_launch(void* const* d_in, const int* in_sizes, int n_in,
                              void* d_out, int out_size) {
    const float* x      = (const float*)d_in[0];
    const float* qkv_w  = (const float*)d_in[1];
    const float* qkv_b  = (const float*)d_in[2];
    const float* attn_w = (const float*)d_in[3];
    const float* attn_b = (const float*)d_in[4];
    const float* proj_w = (const float*)d_in[5];
    const float* proj_b = (const float*)d_in[6];
    float* out = (float*)d_out;

    cudaFuncSetAttribute(k1_qkv,  cudaFuncAttributeMaxDynamicSharedMemorySize, SMEM_G);
    cudaFuncSetAttribute(k2_attn, cudaFuncAttributeMaxDynamicSharedMemorySize, SMEM_K2);
    cudaFuncSetAttribute(k3_proj, cudaFuncAttributeMaxDynamicSharedMemorySize, SMEM_G);

    const int k0n = WSQ * BTAPU2 + NQKVF + NPROJF;
    k0_prep<<<(k0n + 255) / 256, 256>>>(attn_w, qkv_w, proj_w);
    k1_qkv<<<dim3(128, BATCH), 256, SMEM_G>>>(x, qkv_b);
    k2_attn<<<dim3(4, 16, NBH), 512, SMEM_K2>>>(attn_b);
    k3_proj<<<dim3(128, BATCH), 256, SMEM_G>>>(proj_b, out);
}

// round 12
// speedup vs baseline: 1.1885x; 1.1885x over previous
#include <cuda_runtime.h>
#include <cuda_fp16.h>
#include <cstdint>

#define BATCH 4
#define DIMC 96
#define HEADS 3
#define NBH 12
#define WSQ 49
#define QK_SCALE 0.17677669529663687f

// ---- k2 geometry (R9) ----
#define PXB 144
#define HALO_PX 532
#define HALO_BYTES (HALO_PX * PXB)   // 76608
#define BTAPU2 896                   // uint2 per tap: 4 ks * 7 nt * 32 lanes
#define SMEM_K2 HALO_BYTES           // epilogue needs 69120, fits
#define HALO_N 532

// ---- k1/k3 geometry (fp16) ----
#define XSTR 104                     // halfs per px row (96 + 8 pad) -> conflict-free
#define SMEM_G (128 * XSTR * 2)      // 26624 B
#define NQKVF (36 * 6 * 32)          // 6912 fp16 k16 fragments
#define NPROJF (12 * 6 * 32)         // 2304

// ---------------- scratch (device globals) ----------------
__device__ __half g_qkh[(size_t)NBH * 128 * 128 * 64];
__device__ float  g_v  [(size_t)NBH * 32 * 128 * 128];
__device__ float  g_att[(size_t)BATCH * DIMC * 128 * 128];
__device__ uint2  g_w2f[(size_t)WSQ * BTAPU2];
__device__ uint2  g_wqkv[NQKVF];
__device__ uint2  g_wproj[NPROJF];

__device__ __forceinline__ void mma_f16_16n8k16(float* acc, const uint32_t* a, uint2 b) {
    asm volatile(
        "mma.sync.aligned.m16n8k16.row.col.f32.f16.f16.f32 "
        "{%0,%1,%2,%3},{%4,%5,%6,%7},{%8,%9},{%0,%1,%2,%3};"
        : "+f"(acc[0]), "+f"(acc[1]), "+f"(acc[2]), "+f"(acc[3])
        : "r"(a[0]), "r"(a[1]), "r"(a[2]), "r"(a[3]), "r"(b.x), "r"(b.y));
}

__device__ __forceinline__ uint32_t pack_h2(float lo, float hi) {
    __half2 h = __floats2half2_rn(lo, hi);
    return *(uint32_t*)&h;
}

// ---------------- dummy: shifts ncu capture index onto k2 -------------------
__global__ void k_dummy() {}

// ---------------- K0: pack all weight fragments (all fp16) -----------------
__global__ void k0_prep(const float* __restrict__ attn_w,
                        const float* __restrict__ qkv_w,
                        const float* __restrict__ proj_w) {
    int idx = blockIdx.x * 256 + threadIdx.x;
    if (idx < WSQ * BTAPU2) {
        int lane = idx & 31;
        int nt   = (idx >> 5) % 7;
        int ks   = ((idx >> 5) / 7) & 3;
        int s    = idx / (32 * 28);
        int n = nt * 8 + (lane >> 2);
        int k0 = ks * 16 + (lane & 3) * 2;
        uint2 u;
        u.x = (n < WSQ) ? pack_h2(attn_w[(n * 64 + k0) * WSQ + s],
                                  attn_w[(n * 64 + k0 + 1) * WSQ + s]) : 0u;
        u.y = (n < WSQ) ? pack_h2(attn_w[(n * 64 + k0 + 8) * WSQ + s],
                                  attn_w[(n * 64 + k0 + 9) * WSQ + s]) : 0u;
        g_w2f[idx] = u;
        return;
    }
    int i = idx - WSQ * BTAPU2;
    if (i < NQKVF) {
        int lane = i & 31, r = i >> 5;
        int ks = r % 6, nt = r / 6;
        int oc = nt * 8 + (lane >> 2);
        int k  = ks * 16 + (lane & 3) * 2;
        uint2 u;
        u.x = pack_h2(qkv_w[oc * 96 + k],     qkv_w[oc * 96 + k + 1]);
        u.y = pack_h2(qkv_w[oc * 96 + k + 8], qkv_w[oc * 96 + k + 9]);
        g_wqkv[i] = u;
        return;
    }
    i -= NQKVF;
    if (i < NPROJF) {
        int lane = i & 31, r = i >> 5;
        int ks = r % 6, nt = r / 6;
        int oc = nt * 8 + (lane >> 2);
        int k  = ks * 16 + (lane & 3) * 2;
        uint2 u;
        u.x = pack_h2(proj_w[oc * 96 + k],     proj_w[oc * 96 + k + 1]);
        u.y = pack_h2(proj_w[oc * 96 + k + 8], proj_w[oc * 96 + k + 9]);
        g_wproj[i] = u;
    }
}

// ---------------- K1: 1x1 qkv conv via fp16 mma (6 k16-steps) ---------------
__global__ __launch_bounds__(256, 4) void k1_qkv(const float* __restrict__ x,
                                                 const float* __restrict__ bias) {
    extern __shared__ char smemc[];
    __half* xs = (__half*)smemc;                 // [128 px][104]
    const int tid = threadIdx.x, lane = tid & 31, wid = tid >> 5;
    const int row = blockIdx.x, b = blockIdx.y;

    const float4* xb = (const float4*)(x + (((size_t)b * DIMC) << 14) + (row << 7));
    #pragma unroll
    for (int it = 0; it < 12; ++it) {
        int idx = tid + it * 256;                // 3072 groups: c x 4px
        int c = idx >> 5, p4 = idx & 31;
        float4 v = xb[(size_t)c * 4096 + p4];
        int px0 = p4 * 4;
        xs[(px0 + 0) * XSTR + c] = __float2half(v.x);
        xs[(px0 + 1) * XSTR + c] = __float2half(v.y);
        xs[(px0 + 2) * XSTR + c] = __float2half(v.z);
        xs[(px0 + 3) * XSTR + c] = __float2half(v.w);
    }
    __syncthreads();

    const int pr = wid * 16 + (lane >> 2);
    const int c0 = (lane & 3) * 2;
    uint32_t A[6][4];
    #pragma unroll
    for (int ks = 0; ks < 6; ++ks) {
        int kb = ks * 16 + c0;
        A[ks][0] = *(const uint32_t*)&xs[pr * XSTR + kb];
        A[ks][1] = *(const uint32_t*)&xs[(pr + 8) * XSTR + kb];
        A[ks][2] = *(const uint32_t*)&xs[pr * XSTR + kb + 8];
        A[ks][3] = *(const uint32_t*)&xs[(pr + 8) * XSTR + kb + 8];
    }

    const int bh_base = b * HEADS;
    for (int nt = 0; nt < 36; ++nt) {
        uint2 bf[6];
        #pragma unroll
        for (int ks = 0; ks < 6; ++ks) bf[ks] = g_wqkv[(nt * 6 + ks) * 32 + lane];
        float acc[4] = {0.f, 0.f, 0.f, 0.f};
        #pragma unroll
        for (int ks = 0; ks < 6; ++ks) mma_f16_16n8k16(acc, A[ks], bf[ks]);

        int oc = nt * 8 + ((lane & 3) << 1);
        float b0 = bias[oc], b1 = bias[oc + 1];
        if (nt < 24) {
            int oc96 = oc - (nt < 12 ? 0 : 96);
            int head = oc96 >> 5, ch = (oc96 & 31) + (nt < 12 ? 0 : 32);
            size_t base = ((((size_t)(bh_base + head) * 128 + row) << 7));
            float s = (nt < 12) ? QK_SCALE : 1.0f;
            #pragma unroll
            for (int i = 0; i < 2; ++i) {
                int px = pr + i * 8;
                __half2 h = __floats2half2_rn((acc[2 * i] + b0) * s, (acc[2 * i + 1] + b1) * s);
                *(__half2*)&g_qkh[(base + px) * 64 + ch] = h;
            }
        } else {
            int oc96 = oc - 192;
            int head = oc96 >> 5, ch = oc96 & 31;
            float* vb = g_v + ((((size_t)(bh_base + head) * 32) + ch) << 14) + (row << 7);
            #pragma unroll
            for (int i = 0; i < 2; ++i) {
                int px = pr + i * 8;
                vb[px]             = acc[2 * i] + b0;
                vb[(1 << 14) + px] = acc[2 * i + 1] + b1;
            }
        }
    }
}

// ---------------- K2 (R9): fp16 mma logits conv + softmax + attn.V ---------
// 8 warps; warp w owns mtiles {2w,2w+1} x all 7 ntiles. B frags via __ldg.
__global__ __launch_bounds__(256, 2) void k2_attn(const float* __restrict__ attn_b) {
    extern __shared__ char smemk2[];
    float* logits_sh = (float*)smemk2;
    float* v_sh = (float*)(smemk2 + 256 * 50 * 4);

    const int tid = threadIdx.x;
    const int lane = tid & 31, wid = tid >> 5;
    const int bh  = blockIdx.z;
    const int ty0 = blockIdx.y * 8;
    const int tx0 = blockIdx.x * 32;

    uint32_t sb;
    { uint64_t t_; asm("cvta.to.shared.u64 %0, %1;" : "=l"(t_) : "l"(smemk2)); sb = (uint32_t)t_; }

    const uint4* qk4 = (const uint4*)g_qkh;
    for (int idx = tid; idx < HALO_PX * 8; idx += 256) {
        int pxi = idx >> 3, g = idx & 7;
        int hy = pxi / 38, hx = pxi - hy * 38;
        int gy = ty0 - 3 + hy, gx = tx0 - 3 + hx;
        uint4 val = make_uint4(0, 0, 0, 0);
        if ((unsigned)gy < 128u && (unsigned)gx < 128u)
            val = qk4[((((size_t)bh * 128 + gy) << 7) + gx) * 8 + g];
        *(uint4*)(smemk2 + pxi * PXB + g * 16) = val;
    }
    __syncthreads();

    uint32_t abase[2];
    #pragma unroll
    for (int m = 0; m < 2; ++m) {
        int p = (2 * wid + m) * 16 + (lane & 15);
        abase[m] = sb + ((p >> 5) * 38 + (p & 31)) * PXB + (lane >> 4) * 16;
    }

    float acc[2][7][4];
    #pragma unroll
    for (int m = 0; m < 2; ++m)
        #pragma unroll
        for (int nt = 0; nt < 7; ++nt)
            #pragma unroll
            for (int e = 0; e < 4; ++e) acc[m][nt][e] = 0.0f;

    const uint2* wbase = g_w2f + lane;
    #pragma unroll 1
    for (int s = 0; s < WSQ; ++s) {
        int dy = s / 7, dx = s - dy * 7;
        uint32_t toff = (uint32_t)(dy * 38 + dx) * PXB;
        const uint2* wtap = wbase + (size_t)s * BTAPU2;
        #pragma unroll
        for (int ks = 0; ks < 4; ++ks) {
            uint2 bf[7];
            #pragma unroll
            for (int nt = 0; nt < 7; ++nt) bf[nt] = __ldg(wtap + (ks * 7 + nt) * 32);
            uint32_t a[2][4];
            #pragma unroll
            for (int m = 0; m < 2; ++m) {
                asm volatile("ldmatrix.sync.aligned.m8n8.x4.shared.b16 {%0,%1,%2,%3}, [%4];"
                    : "=r"(a[m][0]), "=r"(a[m][1]), "=r"(a[m][2]), "=r"(a[m][3])
                    : "r"(abase[m] + toff + ks * 32));
            }
            #pragma unroll
            for (int nt = 0; nt < 7; ++nt) {
                mma_f16_16n8k16(acc[0][nt], a[0], bf[nt]);
                mma_f16_16n8k16(acc[1][nt], a[1], bf[nt]);
            }
        }
    }

    __syncthreads();

    #pragma unroll
    for (int m = 0; m < 2; ++m) {
        int p0 = (2 * wid + m) * 16 + (lane >> 2);
        #pragma unroll
        for (int nt = 0; nt < 7; ++nt) {
            int t0 = nt * 8 + (lane & 3) * 2;
            if (t0 < WSQ) {
                float bb = attn_b[t0];
                logits_sh[p0 * 50 + t0]       = acc[m][nt][0] + bb;
                logits_sh[(p0 + 8) * 50 + t0] = acc[m][nt][2] + bb;
            }
            if (t0 + 1 < WSQ) {
                float bb = attn_b[t0 + 1];
                logits_sh[p0 * 50 + t0 + 1]       = acc[m][nt][1] + bb;
                logits_sh[(p0 + 8) * 50 + t0 + 1] = acc[m][nt][3] + bb;
            }
        }
    }
    __syncthreads();

    const int py = tid >> 5, px = tid & 31;
    float lg[WSQ];
    float mx = -1e30f;
    #pragma unroll
    for (int t = 0; t < WSQ; ++t) { lg[t] = logits_sh[tid * 50 + t]; mx = fmaxf(mx, lg[t]); }
    float sum = 0.0f;
    #pragma unroll
    for (int t = 0; t < WSQ; ++t) { lg[t] = __expf(lg[t] - mx); sum += lg[t]; }
    float inv = 1.0f / sum;
    #pragma unroll
    for (int t = 0; t < WSQ; ++t) lg[t] *= inv;

    const int b    = bh / HEADS;
    const int head = bh - b * HEADS;

    for (int vcblk = 0; vcblk < 4; ++vcblk) {
        __syncthreads();
        for (int idx = tid; idx < 8 * HALO_N; idx += 256) {
            int cc = idx / HALO_N;
            int rr = idx - cc * HALO_N;
            int hy = rr / 38, hx = rr - hy * 38;
            int gyy = ty0 - 3 + hy, gxx = tx0 - 3 + hx;
            float val = 0.0f;
            if ((unsigned)gyy < 128u && (unsigned)gxx < 128u)
                val = g_v[((((size_t)bh * 32) + vcblk * 8 + cc) << 14) + (gyy << 7) + gxx];
            v_sh[(hy * 40 + hx) * 8 + cc] = val;
        }
        __syncthreads();

        float o[8];
        #pragma unroll
        for (int vc = 0; vc < 8; ++vc) o[vc] = 0.0f;
        #pragma unroll
        for (int dy = 0; dy < 7; ++dy) {
            #pragma unroll
            for (int dx = 0; dx < 7; ++dx) {
                float a = lg[dy * 7 + dx];
                const float4* vp = (const float4*)&v_sh[((py + dy) * 40 + px + dx) * 8];
                float4 v0 = vp[0], v1 = vp[1];
                o[0] = fmaf(a, v0.x, o[0]); o[1] = fmaf(a, v0.y, o[1]);
                o[2] = fmaf(a, v0.z, o[2]); o[3] = fmaf(a, v0.w, o[3]);
                o[4] = fmaf(a, v1.x, o[4]); o[5] = fmaf(a, v1.y, o[5]);
                o[6] = fmaf(a, v1.z, o[6]); o[7] = fmaf(a, v1.w, o[7]);
            }
        }
        #pragma unroll
        for (int vc = 0; vc < 8; ++vc)
            g_att[((((size_t)b * DIMC) + head * 32 + vcblk * 8 + vc) << 14)
                  + ((ty0 + py) << 7) + (tx0 + px)] = o[vc];
    }
}

// ---------------- K3: 1x1 proj via fp16 mma -> d_out ------------------------
__global__ __launch_bounds__(256, 4) void k3_proj(const float* __restrict__ bias,
                                                  float* __restrict__ out) {
    extern __shared__ char smemc[];
    __half* xs = (__half*)smemc;                 // [128 px][104]
    const int tid = threadIdx.x, lane = tid & 31, wid = tid >> 5;
    const int row = blockIdx.x, b = blockIdx.y;

    const float4* xb = (const float4*)(g_att + (((size_t)b * DIMC) << 14) + (row << 7));
    #pragma unroll
    for (int it = 0; it < 12; ++it) {
        int idx = tid + it * 256;
        int c = idx >> 5, p4 = idx & 31;
        float4 v = xb[(size_t)c * 4096 + p4];
        int px0 = p4 * 4;
        xs[(px0 + 0) * XSTR + c] = __float2half(v.x);
        xs[(px0 + 1) * XSTR + c] = __float2half(v.y);
        xs[(px0 + 2) * XSTR + c] = __float2half(v.z);
        xs[(px0 + 3) * XSTR + c] = __float2half(v.w);
    }
    __syncthreads();

    const int pr = wid * 16 + (lane >> 2);
    const int c0 = (lane & 3) * 2;
    uint32_t A[6][4];
    #pragma unroll
    for (int ks = 0; ks < 6; ++ks) {
        int kb = ks * 16 + c0;
        A[ks][0] = *(const uint32_t*)&xs[pr * XSTR + kb];
        A[ks][1] = *(const uint32_t*)&xs[(pr + 8) * XSTR + kb];
        A[ks][2] = *(const uint32_t*)&xs[pr * XSTR + kb + 8];
        A[ks][3] = *(const uint32_t*)&xs[(pr + 8) * XSTR + kb + 8];
    }

    for (int nt = 0; nt < 12; ++nt) {
        uint2 bf[6];
        #pragma unroll
        for (int ks = 0; ks < 6; ++ks) bf[ks] = g_wproj[(nt * 6 + ks) * 32 + lane];
        float acc[4] = {0.f, 0.f, 0.f, 0.f};
        #pragma unroll
        for (int ks = 0; ks < 6; ++ks) mma_f16_16n8k16(acc, A[ks], bf[ks]);

        int oc = nt * 8 + ((lane & 3) << 1);
        float b0 = bias[oc], b1 = bias[oc + 1];
        float* ob = out + ((((size_t)b * DIMC) + oc) << 14) + (row << 7);
        #pragma unroll
        for (int i = 0; i < 2; ++i) {
            int px = pr + i * 8;
            ob[px]             = acc[2 * i] + b0;
            ob[(1 << 14) + px] = acc[2 * i + 1] + b1;
        }
    }
}

// ---------------- launch ---------------------------------------------------
extern "C" void kernel_launch(void* const* d_in, const int* in_sizes, int n_in,
                              void* d_out, int out_size) {
    const float* x      = (const float*)d_in[0];
    const float* qkv_w  = (const float*)d_in[1];
    const float* qkv_b  = (const float*)d_in[2];
    const float* attn_w = (const float*)d_in[3];
    const float* attn_b = (const float*)d_in[4];
    const float* proj_w = (const float*)d_in[5];
    const float* proj_b = (const float*)d_in[6];
    float* out = (float*)d_out;

    cudaFuncSetAttribute(k1_qkv,  cudaFuncAttributeMaxDynamicSharedMemorySize, SMEM_G);
    cudaFuncSetAttribute(k2_attn, cudaFuncAttributeMaxDynamicSharedMemorySize, SMEM_K2);
    cudaFuncSetAttribute(k3_proj, cudaFuncAttributeMaxDynamicSharedMemorySize, SMEM_G);

    k_dummy<<<1, 32>>>();   // shifts ncu's fixed capture index from k3 onto k2
    const int k0n = WSQ * BTAPU2 + NQKVF + NPROJF;
    k0_prep<<<(k0n + 255) / 256, 256>>>(attn_w, qkv_w, proj_w);
    k1_qkv<<<dim3(128, BATCH), 256, SMEM_G>>>(x, qkv_b);
    k2_attn<<<dim3(4, 16, NBH), 256, SMEM_K2>>>(attn_b);
    k3_proj<<<dim3(128, BATCH), 256, SMEM_G>>>(proj_b, out);
}